// round 1
// baseline (speedup 1.0000x reference)
#include <cuda_runtime.h>
#include <math.h>

#define Bn   32
#define Tn   24
#define Cn   512
#define Nn   (Bn*Cn)          // 16384
#define INF  14
#define HIDn 36
#define FFNn 144
#define HDn  18
#define EG   8192
#define NTHREADS 192

// ---------------- scratch (device globals; no allocation in kernel_launch) ----
__device__ float d_xn [Nn*Tn*INF];   // first-half features, [N][T][14]
__device__ float d_xn2[Nn*Tn*INF];   // second-half features, [N][T][14]
__device__ int   d_deg[Cn];
__device__ int   d_colcnt[Cn];
__device__ int   d_off[Cn+1];
__device__ float d_dinv[Cn];
__device__ int   d_brow[EG];
__device__ float d_bw[EG];

// ---------------- K1: per-node degree (rows) and col counts — deterministic ---
__global__ void k_count(const int* __restrict__ ei) {
    int c = blockIdx.x, lane = threadIdx.x;
    int cr = 0, cc = 0;
    for (int e = lane; e < EG; e += 32) {
        cr += (ei[e]      == c);
        cc += (ei[EG + e] == c);
    }
    #pragma unroll
    for (int o = 16; o; o >>= 1) {
        cr += __shfl_down_sync(0xffffffffu, cr, o);
        cc += __shfl_down_sync(0xffffffffu, cc, o);
    }
    if (lane == 0) { d_deg[c] = cr; d_colcnt[c] = cc; }
}

// ---------------- K2: scan col counts -> CSR offsets; dinv --------------------
__global__ void k_scan() {
    __shared__ int s[Cn];
    int t = threadIdx.x;
    s[t] = d_colcnt[t];
    __syncthreads();
    for (int o = 1; o < Cn; o <<= 1) {
        int v = (t >= o) ? s[t - o] : 0;
        __syncthreads();
        s[t] += v;
        __syncthreads();
    }
    d_off[t + 1] = s[t];
    if (t == 0) d_off[0] = 0;
    int dg = d_deg[t];
    d_dinv[t] = (dg > 0) ? (1.0f / sqrtf((float)dg)) : 0.0f;
}

// ---------------- K3: fill CSR buckets, stable in edge order ------------------
__global__ void k_fill(const int* __restrict__ ei) {
    int c = blockIdx.x, lane = threadIdx.x;
    int base = d_off[c];
    float dc = d_dinv[c];
    for (int e0 = 0; e0 < EG; e0 += 32) {
        int e = e0 + lane;
        int col = ei[EG + e];
        bool m = (col == c);
        unsigned mask = __ballot_sync(0xffffffffu, m);
        if (m) {
            int pos = base + __popc(mask & ((1u << lane) - 1u));
            int r = ei[e];
            d_brow[pos] = r;
            d_bw[pos]   = -(d_dinv[r] * dc);   // L_hat = -D^-1/2 A D^-1/2
        }
        base += __popc(mask);
    }
}

// ---------------- K4: pack xn / xn2 into [N][T][14] ---------------------------
__global__ void k_pack(const float* __restrict__ pm, const float* __restrict__ ft) {
    int idx = blockIdx.x * blockDim.x + threadIdx.x;
    if (idx >= Nn * Tn * INF) return;
    int f  = idx % INF;
    int rt = idx / INF;
    int t  = rt % Tn;
    int n  = rt / Tn;
    int b  = n >> 9, c = n & (Cn - 1);
    float v1, v2;
    if (f == 0) {
        v1 = pm[(b * Tn + t) * Cn + c];
        v2 = v1;
    } else {
        v1 = ft[((b * 2 * Tn + t)       * Cn + c) * 13 + (f - 1)];
        v2 = ft[((b * 2 * Tn + Tn + t)  * Cn + c) * 13 + (f - 1)];
    }
    d_xn [idx] = v1;
    d_xn2[idx] = v2;
}

// ---------------- shared-memory matmul: OUT[24][NOUT] = IN[24][KD] @ W + b ----
// column-per-thread, rows blocked by <=6 so each weight LDG feeds 6 FMAs;
// shared reads are warp-broadcast (all lanes of a row-group read same addr).
template<int NOUT, int KD, bool RELU>
__device__ __forceinline__ void mm(const float* __restrict__ sIN,
                                   const float* __restrict__ W,
                                   const float* __restrict__ bias,
                                   float* __restrict__ sOUT, int tid) {
    constexpr int NG = NTHREADS / NOUT;              // row groups
    constexpr int TOTROWS = (Tn + NG - 1) / NG;      // rows per thread
    constexpr int RB = (TOTROWS > 6) ? 6 : TOTROWS;  // row block
    int c = tid % NOUT, g = tid / NOUT;
    if (g >= NG) return;
    float bv = __ldg(bias + c);
    for (int r0 = 0; r0 < TOTROWS; r0 += RB) {
        float acc[RB];
        #pragma unroll
        for (int rr = 0; rr < RB; rr++) acc[rr] = bv;
        #pragma unroll 2
        for (int k = 0; k < KD; k++) {
            float w = __ldg(W + k * NOUT + c);
            #pragma unroll
            for (int rr = 0; rr < RB; rr++) {
                int t = g + (r0 + rr) * NG;
                if (t < Tn) acc[rr] += sIN[t * KD + k] * w;
            }
        }
        #pragma unroll
        for (int rr = 0; rr < RB; rr++) {
            int t = g + (r0 + rr) * NG;
            if (t < Tn) {
                float v = acc[rr];
                if (RELU) v = fmaxf(v, 0.0f);
                sOUT[t * NOUT + c] = v;
            }
        }
    }
}

// ---------------- K5: mega-kernel — one CTA per (batch, city) sequence --------
__global__ __launch_bounds__(NTHREADS, 4)
void k_mega(const float* __restrict__ W0,  const float* __restrict__ W1,
            const float* __restrict__ cb,
            const float* __restrict__ tinW, const float* __restrict__ tinb,
            const float* __restrict__ Wq, const float* __restrict__ bq,
            const float* __restrict__ Wk, const float* __restrict__ bk,
            const float* __restrict__ Wv, const float* __restrict__ bv,
            const float* __restrict__ Wo, const float* __restrict__ bo,
            const float* __restrict__ g1, const float* __restrict__ b1,
            const float* __restrict__ fW1, const float* __restrict__ fb1,
            const float* __restrict__ fW2, const float* __restrict__ fb2,
            const float* __restrict__ g2, const float* __restrict__ b2,
            const float* __restrict__ fcW, const float* __restrict__ fcb,
            float* __restrict__ out) {
    __shared__ float sh_h [Tn * HIDn];   // 864
    __shared__ float sh_q [Tn * HIDn];
    __shared__ float sh_k [Tn * HIDn];
    __shared__ float sh_v [Tn * HIDn];
    __shared__ float sh_o [Tn * HIDn];
    __shared__ float sh_f [Tn * FFNn];   // 3456
    __shared__ float sh_s [2 * Tn * Tn]; // 1152
    __shared__ float sh_x [Tn * INF];    // 336
    __shared__ float sh_tx[Tn * INF];    // 336
    __shared__ float sh_cat[Tn * 28];    // 672  (xn2 | g)

    const int n = blockIdx.x;
    const int b = n >> 9, c = n & (Cn - 1);
    const int tid = threadIdx.x;

    // ---- load self tiles ----
    const float* xn_self  = d_xn  + n * (Tn * INF);
    const float* xn2_self = d_xn2 + n * (Tn * INF);
    for (int idx = tid; idx < Tn * INF; idx += NTHREADS) {
        sh_x[idx] = xn_self[idx];
        int t = idx / INF, f = idx % INF;
        sh_cat[t * 28 + f] = xn2_self[idx];
    }

    // ---- ChebConv T1 term: tx1 = sum_{e: col==c} wgt[e] * xn[b*C + row[e]] ----
    {
        float acc0 = 0.0f, acc1 = 0.0f;
        int start = d_off[c];
        int cnt   = d_off[c + 1] - start;
        for (int i = 0; i < cnt; i++) {
            int   r = __ldg(d_brow + start + i);
            float w = __ldg(d_bw   + start + i);
            const float* nb = d_xn + (b * Cn + r) * (Tn * INF);
            acc0 += w * nb[tid];
            if (tid + NTHREADS < Tn * INF) acc1 += w * nb[tid + NTHREADS];
        }
        sh_tx[tid] = acc0;
        if (tid + NTHREADS < Tn * INF) sh_tx[tid + NTHREADS] = acc1;
    }
    __syncthreads();

    // ---- g = sigmoid(xn @ W0 + tx1 @ W1 + b) -> sh_cat[:,14:] ----
    for (int idx = tid; idx < Tn * INF; idx += NTHREADS) {
        int t = idx / INF, j = idx % INF;
        float s = __ldg(cb + j);
        #pragma unroll
        for (int f = 0; f < INF; f++) {
            s += sh_x [t * INF + f] * __ldg(W0 + f * INF + j);
            s += sh_tx[t * INF + f] * __ldg(W1 + f * INF + j);
        }
        sh_cat[t * 28 + INF + j] = 1.0f / (1.0f + expf(-s));
    }
    __syncthreads();

    // ---- h = cat @ tinW + tinb ----
    mm<HIDn, 28, false>(sh_cat, tinW, tinb, sh_h, tid);
    __syncthreads();

    // ---- add sinusoidal PE ----
    for (int idx = tid; idx < Tn * HIDn; idx += NTHREADS) {
        int t = idx / HIDn, o = idx % HIDn;
        float div = expf(-9.210340371976184f * (float)(o & ~1) / (float)HIDn);
        float ang = (float)t * div;
        sh_h[idx] += (o & 1) ? cosf(ang) : sinf(ang);
    }
    __syncthreads();

    // ---- 2 encoder layers ----
    const float scale = 0.23570226039551584f;  // 1/sqrt(18)
    #pragma unroll 1
    for (int l = 0; l < 2; l++) {
        const float* Wq_l = Wq + l * HIDn * HIDn;  const float* bq_l = bq + l * HIDn;
        const float* Wk_l = Wk + l * HIDn * HIDn;  const float* bk_l = bk + l * HIDn;
        const float* Wv_l = Wv + l * HIDn * HIDn;  const float* bv_l = bv + l * HIDn;
        const float* Wo_l = Wo + l * HIDn * HIDn;  const float* bo_l = bo + l * HIDn;
        const float* g1_l = g1 + l * HIDn;         const float* b1_l = b1 + l * HIDn;
        const float* g2_l = g2 + l * HIDn;         const float* b2_l = b2 + l * HIDn;
        const float* fW1_l = fW1 + l * HIDn * FFNn; const float* fb1_l = fb1 + l * FFNn;
        const float* fW2_l = fW2 + l * FFNn * HIDn; const float* fb2_l = fb2 + l * HIDn;

        mm<HIDn, HIDn, false>(sh_h, Wq_l, bq_l, sh_q, tid);
        mm<HIDn, HIDn, false>(sh_h, Wk_l, bk_l, sh_k, tid);
        mm<HIDn, HIDn, false>(sh_h, Wv_l, bv_l, sh_v, tid);
        __syncthreads();

        // scores s[hh][i][j] = scale * q[i,hh,:] . k[j,hh,:]
        for (int idx = tid; idx < 2 * Tn * Tn; idx += NTHREADS) {
            int hh = idx / (Tn * Tn);
            int r  = idx % (Tn * Tn);
            int i  = r / Tn, j = r % Tn;
            const float* qp = sh_q + i * HIDn + hh * HDn;
            const float* kp = sh_k + j * HIDn + hh * HDn;
            float s = 0.0f;
            #pragma unroll
            for (int d = 0; d < HDn; d++) s += qp[d] * kp[d];
            sh_s[idx] = s * scale;
        }
        __syncthreads();

        // softmax over j (rows = hh*24 + i)
        if (tid < 2 * Tn) {
            float* row = sh_s + tid * Tn;
            float m = row[0];
            #pragma unroll
            for (int j = 1; j < Tn; j++) m = fmaxf(m, row[j]);
            float sum = 0.0f;
            #pragma unroll
            for (int j = 0; j < Tn; j++) { float e = expf(row[j] - m); row[j] = e; sum += e; }
            float inv = 1.0f / sum;
            #pragma unroll
            for (int j = 0; j < Tn; j++) row[j] *= inv;
        }
        __syncthreads();

        // attn output -> sh_q (reuse)
        for (int idx = tid; idx < Tn * HIDn; idx += NTHREADS) {
            int t = idx / HIDn, o = idx % HIDn;
            int hh = o / HDn;
            const float* arow = sh_s + (hh * Tn + t) * Tn;
            float s = 0.0f;
            #pragma unroll
            for (int j = 0; j < Tn; j++) s += arow[j] * sh_v[j * HIDn + o];
            sh_q[idx] = s;
        }
        __syncthreads();

        mm<HIDn, HIDn, false>(sh_q, Wo_l, bo_l, sh_o, tid);
        __syncthreads();

        // LN1: h = LN(h + o)
        if (tid < Tn) {
            float* hr = sh_h + tid * HIDn;
            float* orr = sh_o + tid * HIDn;
            float m = 0.0f;
            #pragma unroll
            for (int k = 0; k < HIDn; k++) { float v = hr[k] + orr[k]; hr[k] = v; m += v; }
            m *= (1.0f / HIDn);
            float var = 0.0f;
            #pragma unroll
            for (int k = 0; k < HIDn; k++) { float d = hr[k] - m; var += d * d; }
            var *= (1.0f / HIDn);
            float rs = rsqrtf(var + 1e-5f);
            #pragma unroll
            for (int k = 0; k < HIDn; k++)
                hr[k] = (hr[k] - m) * rs * __ldg(g1_l + k) + __ldg(b1_l + k);
        }
        __syncthreads();

        // FFN
        mm<FFNn, HIDn, true >(sh_h, fW1_l, fb1_l, sh_f, tid);
        __syncthreads();
        mm<HIDn, FFNn, false>(sh_f, fW2_l, fb2_l, sh_o, tid);
        __syncthreads();

        // LN2: h = LN(h + f2)
        if (tid < Tn) {
            float* hr = sh_h + tid * HIDn;
            float* orr = sh_o + tid * HIDn;
            float m = 0.0f;
            #pragma unroll
            for (int k = 0; k < HIDn; k++) { float v = hr[k] + orr[k]; hr[k] = v; m += v; }
            m *= (1.0f / HIDn);
            float var = 0.0f;
            #pragma unroll
            for (int k = 0; k < HIDn; k++) { float d = hr[k] - m; var += d * d; }
            var *= (1.0f / HIDn);
            float rs = rsqrtf(var + 1e-5f);
            #pragma unroll
            for (int k = 0; k < HIDn; k++)
                hr[k] = (hr[k] - m) * rs * __ldg(g2_l + k) + __ldg(b2_l + k);
        }
        __syncthreads();
    }

    // ---- final fc + store: out[b,t,c] ----
    if (tid < Tn) {
        int t = tid;
        float s = __ldg(fcb);
        const float* hr = sh_h + t * HIDn;
        #pragma unroll
        for (int k = 0; k < HIDn; k++) s += hr[k] * __ldg(fcW + k);
        out[(b * Tn + t) * Cn + c] = s;
    }
}

// ---------------- launch ------------------------------------------------------
extern "C" void kernel_launch(void* const* d_in, const int* in_sizes, int n_in,
                              void* d_out, int out_size) {
    const float *pm, *ft, *W0, *W1, *cb, *tinW, *tinb, *Wq, *bq, *Wk, *bk,
                *Wv, *bv, *Wo, *bo, *g1, *b1, *fW1, *fb1, *fW2, *fb2,
                *g2, *b2, *fcW, *fcb;
    const int* ei;

    if (in_sizes[2] == 2 * EG) {
        // setup_inputs dict order: edge_index at index 2
        pm  = (const float*)d_in[0];  ft  = (const float*)d_in[1];
        ei  = (const int*)  d_in[2];
        W0  = (const float*)d_in[3];  W1  = (const float*)d_in[4];
        cb  = (const float*)d_in[5];
        tinW= (const float*)d_in[6];  tinb= (const float*)d_in[7];
        Wq  = (const float*)d_in[8];  bq  = (const float*)d_in[9];
        Wk  = (const float*)d_in[10]; bk  = (const float*)d_in[11];
        Wv  = (const float*)d_in[12]; bv  = (const float*)d_in[13];
        Wo  = (const float*)d_in[14]; bo  = (const float*)d_in[15];
        g1  = (const float*)d_in[16]; b1  = (const float*)d_in[17];
        fW1 = (const float*)d_in[18]; fb1 = (const float*)d_in[19];
        fW2 = (const float*)d_in[20]; fb2 = (const float*)d_in[21];
        g2  = (const float*)d_in[22]; b2  = (const float*)d_in[23];
        fcW = (const float*)d_in[24]; fcb = (const float*)d_in[25];
    } else {
        // reference-signature order: edge_index last
        pm  = (const float*)d_in[0];  ft  = (const float*)d_in[1];
        W0  = (const float*)d_in[2];  W1  = (const float*)d_in[3];
        cb  = (const float*)d_in[4];
        tinW= (const float*)d_in[5];  tinb= (const float*)d_in[6];
        Wq  = (const float*)d_in[7];  bq  = (const float*)d_in[8];
        Wk  = (const float*)d_in[9];  bk  = (const float*)d_in[10];
        Wv  = (const float*)d_in[11]; bv  = (const float*)d_in[12];
        Wo  = (const float*)d_in[13]; bo  = (const float*)d_in[14];
        g1  = (const float*)d_in[15]; b1  = (const float*)d_in[16];
        fW1 = (const float*)d_in[17]; fb1 = (const float*)d_in[18];
        fW2 = (const float*)d_in[19]; fb2 = (const float*)d_in[20];
        g2  = (const float*)d_in[21]; b2  = (const float*)d_in[22];
        fcW = (const float*)d_in[23]; fcb = (const float*)d_in[24];
        ei  = (const int*)  d_in[25];
    }

    k_count<<<Cn, 32>>>(ei);
    k_scan <<<1, Cn>>>();
    k_fill <<<Cn, 32>>>(ei);
    {
        int total = Nn * Tn * INF;
        k_pack<<<(total + 255) / 256, 256>>>(pm, ft);
    }
    k_mega<<<Nn, NTHREADS>>>(W0, W1, cb, tinW, tinb,
                             Wq, bq, Wk, bk, Wv, bv, Wo, bo,
                             g1, b1, fW1, fb1, fW2, fb2, g2, b2,
                             fcW, fcb, (float*)d_out);
}

// round 4
// speedup vs baseline: 1.7883x; 1.7883x over previous
#include <cuda_runtime.h>
#include <math.h>

#define Bn   32
#define Tn   24
#define Cn   512
#define Nn   (Bn*Cn)          // 16384
#define INF  14
#define HIDn 36
#define FFNn 144
#define HDn  18
#define EG   8192
#define SEQ  2
#define Rn   (SEQ*Tn)         // 48 rows per CTA
#define NT   128

// ---------------- scratch (device globals) -----------------------------------
__device__ float d_xn [Nn*Tn*INF];   // first-half features, [N][T][14] (t*14+f)
__device__ float d_xn2[Nn*Tn*INF];   // second-half features
__device__ int   d_deg[Cn];
__device__ int   d_colcnt[Cn];
__device__ int   d_off[Cn+1];
__device__ float d_dinv[Cn];
__device__ int   d_brow[EG];
__device__ float d_bw[EG];

// ---------------- K1: per-node degree (rows) and col counts ------------------
__global__ void k_count(const int* __restrict__ ei) {
    int c = blockIdx.x, lane = threadIdx.x;
    int cr = 0, cc = 0;
    for (int e = lane; e < EG; e += 32) {
        cr += (ei[e]      == c);
        cc += (ei[EG + e] == c);
    }
    #pragma unroll
    for (int o = 16; o; o >>= 1) {
        cr += __shfl_down_sync(0xffffffffu, cr, o);
        cc += __shfl_down_sync(0xffffffffu, cc, o);
    }
    if (lane == 0) { d_deg[c] = cr; d_colcnt[c] = cc; }
}

// ---------------- K2: scan col counts -> CSR offsets; dinv --------------------
__global__ void k_scan() {
    __shared__ int s[Cn];
    int t = threadIdx.x;
    s[t] = d_colcnt[t];
    __syncthreads();
    for (int o = 1; o < Cn; o <<= 1) {
        int v = (t >= o) ? s[t - o] : 0;
        __syncthreads();
        s[t] += v;
        __syncthreads();
    }
    d_off[t + 1] = s[t];
    if (t == 0) d_off[0] = 0;
    int dg = d_deg[t];
    d_dinv[t] = (dg > 0) ? (1.0f / sqrtf((float)dg)) : 0.0f;
}

// ---------------- K3: fill CSR buckets, stable in edge order ------------------
__global__ void k_fill(const int* __restrict__ ei) {
    int c = blockIdx.x, lane = threadIdx.x;
    int base = d_off[c];
    float dc = d_dinv[c];
    for (int e0 = 0; e0 < EG; e0 += 32) {
        int e = e0 + lane;
        int col = ei[EG + e];
        bool m = (col == c);
        unsigned mask = __ballot_sync(0xffffffffu, m);
        if (m) {
            int pos = base + __popc(mask & ((1u << lane) - 1u));
            int r = ei[e];
            d_brow[pos] = r;
            d_bw[pos]   = -(d_dinv[r] * dc);
        }
        base += __popc(mask);
    }
}

// ---------------- K4: pack xn / xn2 into [N][T][14] ---------------------------
__global__ void k_pack(const float* __restrict__ pm, const float* __restrict__ ft) {
    int idx = blockIdx.x * blockDim.x + threadIdx.x;
    if (idx >= Nn * Tn * INF) return;
    int f  = idx % INF;
    int rt = idx / INF;
    int t  = rt % Tn;
    int n  = rt / Tn;
    int b  = n >> 9, c = n & (Cn - 1);
    float v1, v2;
    if (f == 0) {
        v1 = pm[(b * Tn + t) * Cn + c];
        v2 = v1;
    } else {
        v1 = ft[((b * 2 * Tn + t)       * Cn + c) * 13 + (f - 1)];
        v2 = ft[((b * 2 * Tn + Tn + t)  * Cn + c) * 13 + (f - 1)];
    }
    d_xn [idx] = v1;
    d_xn2[idx] = v2;
}

// ---------------- register-tiled matmul: sOUT[NOUT][48] = W^T @ sIN ----------
// sIN column-major [KD][48]; W global row-major [KD][NOUT]; sOUT col-major.
// 4x4 tiles: per k-iter 1 LDS.128 + 1 LDG.128 + 16 FFMA.
template<int KD, int NOUT, bool RELU>
__device__ __forceinline__ void mmT(const float* __restrict__ sIN,
                                    const float* __restrict__ W,
                                    const float* __restrict__ bias,
                                    float* __restrict__ sOUT, int tid) {
    constexpr int RG = Rn / 4;                    // 12 row groups
    constexpr int TILES = RG * (NOUT / 4);
    for (int tile = tid; tile < TILES; tile += NT) {
        int rg = tile % RG, cg = tile / RG;
        const float* aP = sIN + rg * 4;
        const float* wP = W + cg * 4;
        float b0 = __ldg(bias + cg * 4 + 0);
        float b1 = __ldg(bias + cg * 4 + 1);
        float b2 = __ldg(bias + cg * 4 + 2);
        float b3 = __ldg(bias + cg * 4 + 3);
        float4 c0 = make_float4(b0, b0, b0, b0);
        float4 c1 = make_float4(b1, b1, b1, b1);
        float4 c2 = make_float4(b2, b2, b2, b2);
        float4 c3 = make_float4(b3, b3, b3, b3);
        #pragma unroll 4
        for (int k = 0; k < KD; k++) {
            float4 a = *(const float4*)(aP + k * Rn);
            float4 w = __ldg((const float4*)(wP + k * NOUT));
            c0.x = fmaf(a.x, w.x, c0.x); c0.y = fmaf(a.y, w.x, c0.y);
            c0.z = fmaf(a.z, w.x, c0.z); c0.w = fmaf(a.w, w.x, c0.w);
            c1.x = fmaf(a.x, w.y, c1.x); c1.y = fmaf(a.y, w.y, c1.y);
            c1.z = fmaf(a.z, w.y, c1.z); c1.w = fmaf(a.w, w.y, c1.w);
            c2.x = fmaf(a.x, w.z, c2.x); c2.y = fmaf(a.y, w.z, c2.y);
            c2.z = fmaf(a.z, w.z, c2.z); c2.w = fmaf(a.w, w.z, c2.w);
            c3.x = fmaf(a.x, w.w, c3.x); c3.y = fmaf(a.y, w.w, c3.y);
            c3.z = fmaf(a.z, w.w, c3.z); c3.w = fmaf(a.w, w.w, c3.w);
        }
        if (RELU) {
            c0.x = fmaxf(c0.x, 0.f); c0.y = fmaxf(c0.y, 0.f); c0.z = fmaxf(c0.z, 0.f); c0.w = fmaxf(c0.w, 0.f);
            c1.x = fmaxf(c1.x, 0.f); c1.y = fmaxf(c1.y, 0.f); c1.z = fmaxf(c1.z, 0.f); c1.w = fmaxf(c1.w, 0.f);
            c2.x = fmaxf(c2.x, 0.f); c2.y = fmaxf(c2.y, 0.f); c2.z = fmaxf(c2.z, 0.f); c2.w = fmaxf(c2.w, 0.f);
            c3.x = fmaxf(c3.x, 0.f); c3.y = fmaxf(c3.y, 0.f); c3.z = fmaxf(c3.z, 0.f); c3.w = fmaxf(c3.w, 0.f);
        }
        *(float4*)(sOUT + (cg * 4 + 0) * Rn + rg * 4) = c0;
        *(float4*)(sOUT + (cg * 4 + 1) * Rn + rg * 4) = c1;
        *(float4*)(sOUT + (cg * 4 + 2) * Rn + rg * 4) = c2;
        *(float4*)(sOUT + (cg * 4 + 3) * Rn + rg * 4) = c3;
    }
}

// ---------------- K5: mega-kernel — 2 sequences per CTA, static smem ----------
// smem (floats):
//   sh_h : [36*48]  = 1728
//   sh_U : [144*48] = 6912  (q@0, k@1728, v@3456, o@5184; ffn hidden = whole U;
//                            cheb x@0, tx@672, cat@1344 — used before q exists)
//   sh_S : [2304]   (scores [j=24][96 rows]; later ffn2-out [36][48]=1728)
// total 10944 floats = 43776 B  (static, no opt-in needed)
__global__ __launch_bounds__(NT, 4)
void k_mega(const float* __restrict__ W0,  const float* __restrict__ W1,
            const float* __restrict__ cb,
            const float* __restrict__ tinW, const float* __restrict__ tinb,
            const float* __restrict__ Wq, const float* __restrict__ bq,
            const float* __restrict__ Wk, const float* __restrict__ bk,
            const float* __restrict__ Wv, const float* __restrict__ bv,
            const float* __restrict__ Wo, const float* __restrict__ bo,
            const float* __restrict__ g1, const float* __restrict__ b1,
            const float* __restrict__ fW1, const float* __restrict__ fb1,
            const float* __restrict__ fW2, const float* __restrict__ fb2,
            const float* __restrict__ g2, const float* __restrict__ b2,
            const float* __restrict__ fcW, const float* __restrict__ fcb,
            float* __restrict__ out) {
    __shared__ float sh_h[HIDn * Rn];     // 1728
    __shared__ float sh_U[FFNn * Rn];     // 6912
    __shared__ float sh_S[2304];

    float* h = sh_h;
    float* U = sh_U;
    float* S = sh_S;
    float* x   = U;            //  672
    float* tx  = U + 672;      //  672
    float* cat = U + 1344;     // 1344

    const int tid = threadIdx.x;
    const int nbase = blockIdx.x * SEQ;

    // ---- stage self tiles (col-major [14][48]) ----
    for (int idx = tid; idx < SEQ * Tn * INF; idx += NT) {
        int s2 = idx / 336, u = idx % 336;
        int t = u / INF, f = u % INF;
        int n2 = nbase + s2;
        x  [f * Rn + s2 * Tn + t] = d_xn [n2 * 336 + u];
        cat[f * Rn + s2 * Tn + t] = d_xn2[n2 * 336 + u];
    }

    // ---- ChebConv gather: 64 threads per sequence ----
    {
        int s2 = tid >> 6, l = tid & 63;
        int n2 = nbase + s2;
        int b = n2 >> 9, c = n2 & (Cn - 1);
        float acc[6];
        #pragma unroll
        for (int i = 0; i < 6; i++) acc[i] = 0.0f;
        int start = d_off[c], end = d_off[c + 1];
        for (int e = start; e < end; e++) {
            int   rr = __ldg(d_brow + e);
            float w  = __ldg(d_bw + e);
            const float* nb = d_xn + (b * Cn + rr) * 336;
            #pragma unroll
            for (int i = 0; i < 6; i++) {
                int u = l + i * 64;
                if (u < 336) acc[i] = fmaf(w, nb[u], acc[i]);
            }
        }
        #pragma unroll
        for (int i = 0; i < 6; i++) {
            int u = l + i * 64;
            if (u < 336) {
                int t = u / INF, f = u % INF;
                tx[f * Rn + s2 * Tn + t] = acc[i];
            }
        }
    }
    __syncthreads();

    // ---- gate: cat[:,14:] = sigmoid(x @ W0 + tx @ W1 + cb) ----
    for (int idx = tid; idx < Rn * INF; idx += NT) {
        int r = idx % Rn, j = idx / Rn;
        float sacc = __ldg(cb + j);
        #pragma unroll
        for (int f = 0; f < INF; f++) {
            sacc = fmaf(x [f * Rn + r], __ldg(W0 + f * INF + j), sacc);
            sacc = fmaf(tx[f * Rn + r], __ldg(W1 + f * INF + j), sacc);
        }
        cat[(INF + j) * Rn + r] = 1.0f / (1.0f + expf(-sacc));
    }
    __syncthreads();

    // ---- h = cat @ tinW + tinb ----
    mmT<28, HIDn, false>(cat, tinW, tinb, h, tid);
    __syncthreads();

    // ---- sinusoidal PE ----
    for (int idx = tid; idx < HIDn * Rn; idx += NT) {
        int r = idx % Rn, o = idx / Rn;
        int t = r % Tn;
        float div = expf(-9.210340371976184f * (float)(o & ~1) / (float)HIDn);
        float ang = (float)t * div;
        h[idx] += (o & 1) ? cosf(ang) : sinf(ang);
    }
    __syncthreads();

    // ---- 2 encoder layers ----
    const float scale = 0.23570226039551584f;  // 1/sqrt(18)
    #pragma unroll 1
    for (int l = 0; l < 2; l++) {
        const float* Wq_l = Wq + l * HIDn * HIDn;  const float* bq_l = bq + l * HIDn;
        const float* Wk_l = Wk + l * HIDn * HIDn;  const float* bk_l = bk + l * HIDn;
        const float* Wv_l = Wv + l * HIDn * HIDn;  const float* bv_l = bv + l * HIDn;
        const float* Wo_l = Wo + l * HIDn * HIDn;  const float* bo_l = bo + l * HIDn;
        const float* g1_l = g1 + l * HIDn;         const float* b1_l = b1 + l * HIDn;
        const float* g2_l = g2 + l * HIDn;         const float* b2_l = b2 + l * HIDn;
        const float* fW1_l = fW1 + l * HIDn * FFNn; const float* fb1_l = fb1 + l * FFNn;
        const float* fW2_l = fW2 + l * FFNn * HIDn; const float* fb2_l = fb2 + l * HIDn;

        mmT<HIDn, HIDn, false>(h, Wq_l, bq_l, U,        tid);
        mmT<HIDn, HIDn, false>(h, Wk_l, bk_l, U + 1728, tid);
        mmT<HIDn, HIDn, false>(h, Wv_l, bv_l, U + 3456, tid);
        __syncthreads();

        // scores S[j*96 + row], row = s2*48 + hh*24 + i
        for (int idx = tid; idx < 24 * 96; idx += NT) {
            int row = idx % 96, j = idx / 96;
            int i = row % 24, hh = (row / 24) & 1, s2 = row / 48;
            const float* qp = U        + (hh * HDn) * Rn + s2 * Tn + i;
            const float* kp = U + 1728 + (hh * HDn) * Rn + s2 * Tn + j;
            float acc = 0.0f;
            #pragma unroll
            for (int d = 0; d < HDn; d++) acc = fmaf(qp[d * Rn], kp[d * Rn], acc);
            S[idx] = acc * scale;
        }
        __syncthreads();

        // softmax over j (row per thread; stride-96 → bank per tid, conflict-free)
        if (tid < 96) {
            float m = S[tid];
            #pragma unroll
            for (int j = 1; j < Tn; j++) m = fmaxf(m, S[j * 96 + tid]);
            float sum = 0.0f;
            #pragma unroll
            for (int j = 0; j < Tn; j++) {
                float e = expf(S[j * 96 + tid] - m);
                S[j * 96 + tid] = e;
                sum += e;
            }
            float inv = 1.0f / sum;
            #pragma unroll
            for (int j = 0; j < Tn; j++) S[j * 96 + tid] *= inv;
        }
        __syncthreads();

        // attn out -> q region (U[0..1728))
        for (int idx = tid; idx < HIDn * Rn; idx += NT) {
            int r = idx % Rn, o = idx / Rn;
            int s2 = r / Tn, t = r % Tn;
            int hh = o / HDn;
            const float* ap = S + (s2 * 48 + hh * 24 + t);
            const float* vp = U + 3456 + o * Rn + s2 * Tn;
            float acc = 0.0f;
            #pragma unroll
            for (int j = 0; j < Tn; j++) acc = fmaf(ap[j * 96], vp[j], acc);
            U[idx] = acc;
        }
        __syncthreads();

        mmT<HIDn, HIDn, false>(U, Wo_l, bo_l, U + 5184, tid);
        __syncthreads();

        // LN1: h = LN(h + o)
        if (tid < Rn) {
            int r = tid;
            float m = 0.0f, q2 = 0.0f;
            #pragma unroll
            for (int k = 0; k < HIDn; k++) {
                float v = h[k * Rn + r] + U[5184 + k * Rn + r];
                h[k * Rn + r] = v;
                m += v; q2 += v * v;
            }
            m *= (1.0f / HIDn);
            float var = q2 * (1.0f / HIDn) - m * m;
            float rs = rsqrtf(var + 1e-5f);
            #pragma unroll
            for (int k = 0; k < HIDn; k++)
                h[k * Rn + r] = (h[k * Rn + r] - m) * rs * __ldg(g1_l + k) + __ldg(b1_l + k);
        }
        __syncthreads();

        // FFN
        mmT<HIDn, FFNn, true >(h, fW1_l, fb1_l, U, tid);
        __syncthreads();
        mmT<FFNn, HIDn, false>(U, fW2_l, fb2_l, S, tid);
        __syncthreads();

        // LN2: h = LN(h + f2)
        if (tid < Rn) {
            int r = tid;
            float m = 0.0f, q2 = 0.0f;
            #pragma unroll
            for (int k = 0; k < HIDn; k++) {
                float v = h[k * Rn + r] + S[k * Rn + r];
                h[k * Rn + r] = v;
                m += v; q2 += v * v;
            }
            m *= (1.0f / HIDn);
            float var = q2 * (1.0f / HIDn) - m * m;
            float rs = rsqrtf(var + 1e-5f);
            #pragma unroll
            for (int k = 0; k < HIDn; k++)
                h[k * Rn + r] = (h[k * Rn + r] - m) * rs * __ldg(g2_l + k) + __ldg(b2_l + k);
        }
        __syncthreads();
    }

    // ---- final fc + store ----
    if (tid < Rn) {
        int r = tid;
        int s2 = r / Tn, t = r % Tn;
        int n2 = nbase + s2;
        int b = n2 >> 9, c = n2 & (Cn - 1);
        float acc = __ldg(fcb);
        #pragma unroll
        for (int k = 0; k < HIDn; k++) acc = fmaf(h[k * Rn + r], __ldg(fcW + k), acc);
        out[(b * Tn + t) * Cn + c] = acc;
    }
}

// ---------------- launch ------------------------------------------------------
extern "C" void kernel_launch(void* const* d_in, const int* in_sizes, int n_in,
                              void* d_out, int out_size) {
    const float *pm, *ft, *W0, *W1, *cb, *tinW, *tinb, *Wq, *bq, *Wk, *bk,
                *Wv, *bv, *Wo, *bo, *g1, *b1, *fW1, *fb1, *fW2, *fb2,
                *g2, *b2, *fcW, *fcb;
    const int* ei;

    if (in_sizes[2] == 2 * EG) {
        pm  = (const float*)d_in[0];  ft  = (const float*)d_in[1];
        ei  = (const int*)  d_in[2];
        W0  = (const float*)d_in[3];  W1  = (const float*)d_in[4];
        cb  = (const float*)d_in[5];
        tinW= (const float*)d_in[6];  tinb= (const float*)d_in[7];
        Wq  = (const float*)d_in[8];  bq  = (const float*)d_in[9];
        Wk  = (const float*)d_in[10]; bk  = (const float*)d_in[11];
        Wv  = (const float*)d_in[12]; bv  = (const float*)d_in[13];
        Wo  = (const float*)d_in[14]; bo  = (const float*)d_in[15];
        g1  = (const float*)d_in[16]; b1  = (const float*)d_in[17];
        fW1 = (const float*)d_in[18]; fb1 = (const float*)d_in[19];
        fW2 = (const float*)d_in[20]; fb2 = (const float*)d_in[21];
        g2  = (const float*)d_in[22]; b2  = (const float*)d_in[23];
        fcW = (const float*)d_in[24]; fcb = (const float*)d_in[25];
    } else {
        pm  = (const float*)d_in[0];  ft  = (const float*)d_in[1];
        W0  = (const float*)d_in[2];  W1  = (const float*)d_in[3];
        cb  = (const float*)d_in[4];
        tinW= (const float*)d_in[5];  tinb= (const float*)d_in[6];
        Wq  = (const float*)d_in[7];  bq  = (const float*)d_in[8];
        Wk  = (const float*)d_in[9];  bk  = (const float*)d_in[10];
        Wv  = (const float*)d_in[11]; bv  = (const float*)d_in[12];
        Wo  = (const float*)d_in[13]; bo  = (const float*)d_in[14];
        g1  = (const float*)d_in[15]; b1  = (const float*)d_in[16];
        fW1 = (const float*)d_in[17]; fb1 = (const float*)d_in[18];
        fW2 = (const float*)d_in[19]; fb2 = (const float*)d_in[20];
        g2  = (const float*)d_in[21]; b2  = (const float*)d_in[22];
        fcW = (const float*)d_in[23]; fcb = (const float*)d_in[24];
        ei  = (const int*)  d_in[25];
    }

    k_count<<<Cn, 32>>>(ei);
    k_scan <<<1, Cn>>>();
    k_fill <<<Cn, 32>>>(ei);
    {
        int total = Nn * Tn * INF;
        k_pack<<<(total + 255) / 256, 256>>>(pm, ft);
    }
    k_mega<<<Nn / SEQ, NT>>>(W0, W1, cb, tinW, tinb,
                             Wq, bq, Wk, bk, Wv, bv, Wo, bo,
                             g1, b1, fW1, fb1, fW2, fb2, g2, b2,
                             fcW, fcb, (float*)d_out);
}

// round 6
// speedup vs baseline: 1.8238x; 1.0199x over previous
#include <cuda_runtime.h>
#include <math.h>
#include <stdint.h>

#define Bn   32
#define Tn   24
#define Cn   512
#define Nn   (Bn*Cn)          // 16384
#define INF  14
#define HIDn 36
#define FFNn 144
#define HDn  18
#define EG   8192
#define SEQ  2
#define Rn   (SEQ*Tn)         // 48 rows per CTA
#define NT   128

// ---------------- scratch (device globals) -----------------------------------
__device__ float d_xn [Nn*Tn*INF];   // first-half features, [N][T][14] (t*14+f)
__device__ float d_xn2[Nn*Tn*INF];   // second-half features
__device__ int   d_deg[Cn];
__device__ int   d_colcnt[Cn];
__device__ int   d_off[Cn+1];
__device__ float d_dinv[Cn];
__device__ int   d_brow[EG];
__device__ float d_bw[EG];

// ---------------- K1: per-node degree (rows) and col counts ------------------
__global__ void k_count(const int* __restrict__ ei) {
    int c = blockIdx.x, lane = threadIdx.x;
    int cr = 0, cc = 0;
    for (int e = lane; e < EG; e += 32) {
        cr += (ei[e]      == c);
        cc += (ei[EG + e] == c);
    }
    #pragma unroll
    for (int o = 16; o; o >>= 1) {
        cr += __shfl_down_sync(0xffffffffu, cr, o);
        cc += __shfl_down_sync(0xffffffffu, cc, o);
    }
    if (lane == 0) { d_deg[c] = cr; d_colcnt[c] = cc; }
}

// ---------------- K2: scan col counts -> CSR offsets; dinv --------------------
__global__ void k_scan() {
    __shared__ int s[Cn];
    int t = threadIdx.x;
    s[t] = d_colcnt[t];
    __syncthreads();
    for (int o = 1; o < Cn; o <<= 1) {
        int v = (t >= o) ? s[t - o] : 0;
        __syncthreads();
        s[t] += v;
        __syncthreads();
    }
    d_off[t + 1] = s[t];
    if (t == 0) d_off[0] = 0;
    int dg = d_deg[t];
    d_dinv[t] = (dg > 0) ? (1.0f / sqrtf((float)dg)) : 0.0f;
}

// ---------------- K3: fill CSR buckets, stable in edge order ------------------
__global__ void k_fill(const int* __restrict__ ei) {
    int c = blockIdx.x, lane = threadIdx.x;
    int base = d_off[c];
    float dc = d_dinv[c];
    for (int e0 = 0; e0 < EG; e0 += 32) {
        int e = e0 + lane;
        int col = ei[EG + e];
        bool m = (col == c);
        unsigned mask = __ballot_sync(0xffffffffu, m);
        if (m) {
            int pos = base + __popc(mask & ((1u << lane) - 1u));
            int r = ei[e];
            d_brow[pos] = r;
            d_bw[pos]   = -(d_dinv[r] * dc);
        }
        base += __popc(mask);
    }
}

// ---------------- K4: pack xn / xn2 into [N][T][14] ---------------------------
__global__ void k_pack(const float* __restrict__ pm, const float* __restrict__ ft) {
    int idx = blockIdx.x * blockDim.x + threadIdx.x;
    if (idx >= Nn * Tn * INF) return;
    int f  = idx % INF;
    int rt = idx / INF;
    int t  = rt % Tn;
    int n  = rt / Tn;
    int b  = n >> 9, c = n & (Cn - 1);
    float v1, v2;
    if (f == 0) {
        v1 = pm[(b * Tn + t) * Cn + c];
        v2 = v1;
    } else {
        v1 = ft[((b * 2 * Tn + t)       * Cn + c) * 13 + (f - 1)];
        v2 = ft[((b * 2 * Tn + Tn + t)  * Cn + c) * 13 + (f - 1)];
    }
    d_xn [idx] = v1;
    d_xn2[idx] = v2;
}

// ---------------- packed f32x2 helpers ----------------------------------------
__device__ __forceinline__ uint64_t pack2(float v) {
    uint64_t r;
    asm("mov.b64 %0, {%1, %1};" : "=l"(r) : "f"(v));
    return r;
}
__device__ __forceinline__ void fma2(uint64_t& acc, uint64_t a, uint64_t b) {
    asm("fma.rn.f32x2 %0, %1, %2, %0;" : "+l"(acc) : "l"(a), "l"(b));
}
__device__ __forceinline__ float2 unpack2(uint64_t v) {
    float lo, hi;
    asm("mov.b64 {%0, %1}, %2;" : "=f"(lo), "=f"(hi) : "l"(v));
    return make_float2(lo, hi);
}

// ---------------- register-tiled matmul with FFMA2 ---------------------------
// sOUT[NOUT][48] = W^T @ sIN (+bias).  sIN col-major [KD][48]; W row-major
// [KD][NOUT].  4x4 tiles; rows pre-packed as f32x2 pairs via 128-bit LDS.
// per k-iter: 1 LDS.128 + 1 LDG.128 + 4 packs (alu) + 8 FFMA2 (fma, 16 cyc).
template<int KD, int NOUT, bool RELU>
__device__ __forceinline__ void mmT(const float* __restrict__ sIN,
                                    const float* __restrict__ W,
                                    const float* __restrict__ bias,
                                    float* __restrict__ sOUT, int tid) {
    constexpr int RG = Rn / 4;                    // 12 row groups
    constexpr int TILES = RG * (NOUT / 4);
    for (int tile = tid; tile < TILES; tile += NT) {
        int rg = tile % RG, cg = tile / RG;
        const float* aP = sIN + rg * 4;
        const float* wP = W + cg * 4;
        // acc[2*j] = rows {0,1}, acc[2*j+1] = rows {2,3} of column cg*4+j
        uint64_t acc[8];
        #pragma unroll
        for (int j = 0; j < 4; j++) {
            uint64_t bp = pack2(__ldg(bias + cg * 4 + j));
            acc[2 * j]     = bp;
            acc[2 * j + 1] = bp;
        }
        #pragma unroll 4
        for (int k = 0; k < KD; k++) {
            ulonglong2 av = *(const ulonglong2*)(aP + k * Rn);   // LDS.128: 4 rows = 2 pairs
            float4 w = __ldg((const float4*)(wP + k * NOUT));
            uint64_t w0 = pack2(w.x), w1 = pack2(w.y), w2 = pack2(w.z), w3 = pack2(w.w);
            fma2(acc[0], av.x, w0); fma2(acc[1], av.y, w0);
            fma2(acc[2], av.x, w1); fma2(acc[3], av.y, w1);
            fma2(acc[4], av.x, w2); fma2(acc[5], av.y, w2);
            fma2(acc[6], av.x, w3); fma2(acc[7], av.y, w3);
        }
        #pragma unroll
        for (int j = 0; j < 4; j++) {
            float2 lo = unpack2(acc[2 * j]);
            float2 hi = unpack2(acc[2 * j + 1]);
            float4 c;
            c.x = lo.x; c.y = lo.y; c.z = hi.x; c.w = hi.y;
            if (RELU) {
                c.x = fmaxf(c.x, 0.f); c.y = fmaxf(c.y, 0.f);
                c.z = fmaxf(c.z, 0.f); c.w = fmaxf(c.w, 0.f);
            }
            *(float4*)(sOUT + (cg * 4 + j) * Rn + rg * 4) = c;
        }
    }
}

// ---------------- K5: mega-kernel — 2 sequences per CTA, static smem ----------
// smem (floats):
//   sh_h : [36*48]  = 1728
//   sh_U : [144*48] = 6912  (q@0, k@1728, v@3456, o@5184; ffn hidden = whole U;
//                            cheb x@0, tx@672, cat@1344 — used before q exists)
//   sh_S : [2304]   (scores [j=24][96 rows]; later ffn2-out [36][48]=1728)
// total 10944 floats = 43776 B  (static, no opt-in needed)
__global__ __launch_bounds__(NT, 4)
void k_mega(const float* __restrict__ W0,  const float* __restrict__ W1,
            const float* __restrict__ cb,
            const float* __restrict__ tinW, const float* __restrict__ tinb,
            const float* __restrict__ Wq, const float* __restrict__ bq,
            const float* __restrict__ Wk, const float* __restrict__ bk,
            const float* __restrict__ Wv, const float* __restrict__ bv,
            const float* __restrict__ Wo, const float* __restrict__ bo,
            const float* __restrict__ g1, const float* __restrict__ b1,
            const float* __restrict__ fW1, const float* __restrict__ fb1,
            const float* __restrict__ fW2, const float* __restrict__ fb2,
            const float* __restrict__ g2, const float* __restrict__ b2,
            const float* __restrict__ fcW, const float* __restrict__ fcb,
            float* __restrict__ out) {
    __shared__ __align__(16) float sh_h[HIDn * Rn];     // 1728
    __shared__ __align__(16) float sh_U[FFNn * Rn];     // 6912
    __shared__ __align__(16) float sh_S[2304];

    float* h = sh_h;
    float* U = sh_U;
    float* S = sh_S;
    float* x   = U;            //  672
    float* tx  = U + 672;      //  672
    float* cat = U + 1344;     // 1344

    const int tid = threadIdx.x;
    const int nbase = blockIdx.x * SEQ;

    // ---- stage self tiles (col-major [14][48]) ----
    for (int idx = tid; idx < SEQ * Tn * INF; idx += NT) {
        int s2 = idx / 336, u = idx % 336;
        int t = u / INF, f = u % INF;
        int n2 = nbase + s2;
        x  [f * Rn + s2 * Tn + t] = d_xn [n2 * 336 + u];
        cat[f * Rn + s2 * Tn + t] = d_xn2[n2 * 336 + u];
    }

    // ---- ChebConv gather: 64 threads per sequence ----
    {
        int s2 = tid >> 6, l = tid & 63;
        int n2 = nbase + s2;
        int b = n2 >> 9, c = n2 & (Cn - 1);
        float acc[6];
        #pragma unroll
        for (int i = 0; i < 6; i++) acc[i] = 0.0f;
        int start = d_off[c], end = d_off[c + 1];
        for (int e = start; e < end; e++) {
            int   rr = __ldg(d_brow + e);
            float w  = __ldg(d_bw + e);
            const float* nb = d_xn + (b * Cn + rr) * 336;
            #pragma unroll
            for (int i = 0; i < 6; i++) {
                int u = l + i * 64;
                if (u < 336) acc[i] = fmaf(w, nb[u], acc[i]);
            }
        }
        #pragma unroll
        for (int i = 0; i < 6; i++) {
            int u = l + i * 64;
            if (u < 336) {
                int t = u / INF, f = u % INF;
                tx[f * Rn + s2 * Tn + t] = acc[i];
            }
        }
    }
    __syncthreads();

    // ---- gate: cat[:,14:] = sigmoid(x @ W0 + tx @ W1 + cb) ----
    for (int idx = tid; idx < Rn * INF; idx += NT) {
        int r = idx % Rn, j = idx / Rn;
        float sacc = __ldg(cb + j);
        #pragma unroll
        for (int f = 0; f < INF; f++) {
            sacc = fmaf(x [f * Rn + r], __ldg(W0 + f * INF + j), sacc);
            sacc = fmaf(tx[f * Rn + r], __ldg(W1 + f * INF + j), sacc);
        }
        cat[(INF + j) * Rn + r] = 1.0f / (1.0f + expf(-sacc));
    }
    __syncthreads();

    // ---- h = cat @ tinW + tinb ----
    mmT<28, HIDn, false>(cat, tinW, tinb, h, tid);
    __syncthreads();

    // ---- sinusoidal PE ----
    for (int idx = tid; idx < HIDn * Rn; idx += NT) {
        int r = idx % Rn, o = idx / Rn;
        int t = r % Tn;
        float div = expf(-9.210340371976184f * (float)(o & ~1) / (float)HIDn);
        float ang = (float)t * div;
        h[idx] += (o & 1) ? cosf(ang) : sinf(ang);
    }
    __syncthreads();

    // ---- 2 encoder layers ----
    const float scale = 0.23570226039551584f;  // 1/sqrt(18)
    #pragma unroll 1
    for (int l = 0; l < 2; l++) {
        const float* Wq_l = Wq + l * HIDn * HIDn;  const float* bq_l = bq + l * HIDn;
        const float* Wk_l = Wk + l * HIDn * HIDn;  const float* bk_l = bk + l * HIDn;
        const float* Wv_l = Wv + l * HIDn * HIDn;  const float* bv_l = bv + l * HIDn;
        const float* Wo_l = Wo + l * HIDn * HIDn;  const float* bo_l = bo + l * HIDn;
        const float* g1_l = g1 + l * HIDn;         const float* b1_l = b1 + l * HIDn;
        const float* g2_l = g2 + l * HIDn;         const float* b2_l = b2 + l * HIDn;
        const float* fW1_l = fW1 + l * HIDn * FFNn; const float* fb1_l = fb1 + l * FFNn;
        const float* fW2_l = fW2 + l * FFNn * HIDn; const float* fb2_l = fb2 + l * HIDn;

        mmT<HIDn, HIDn, false>(h, Wq_l, bq_l, U,        tid);
        mmT<HIDn, HIDn, false>(h, Wk_l, bk_l, U + 1728, tid);
        mmT<HIDn, HIDn, false>(h, Wv_l, bv_l, U + 3456, tid);
        __syncthreads();

        // scores S[j*96 + row], row = s2*48 + hh*24 + i
        for (int idx = tid; idx < 24 * 96; idx += NT) {
            int row = idx % 96, j = idx / 96;
            int i = row % 24, hh = (row / 24) & 1, s2 = row / 48;
            const float* qp = U        + (hh * HDn) * Rn + s2 * Tn + i;
            const float* kp = U + 1728 + (hh * HDn) * Rn + s2 * Tn + j;
            float acc = 0.0f;
            #pragma unroll
            for (int d = 0; d < HDn; d++) acc = fmaf(qp[d * Rn], kp[d * Rn], acc);
            S[idx] = acc * scale;
        }
        __syncthreads();

        // softmax over j (row per thread; stride-96 → bank per tid, conflict-free)
        if (tid < 96) {
            float m = S[tid];
            #pragma unroll
            for (int j = 1; j < Tn; j++) m = fmaxf(m, S[j * 96 + tid]);
            float sum = 0.0f;
            #pragma unroll
            for (int j = 0; j < Tn; j++) {
                float e = expf(S[j * 96 + tid] - m);
                S[j * 96 + tid] = e;
                sum += e;
            }
            float inv = 1.0f / sum;
            #pragma unroll
            for (int j = 0; j < Tn; j++) S[j * 96 + tid] *= inv;
        }
        __syncthreads();

        // attn out -> q region (U[0..1728))
        for (int idx = tid; idx < HIDn * Rn; idx += NT) {
            int r = idx % Rn, o = idx / Rn;
            int s2 = r / Tn, t = r % Tn;
            int hh = o / HDn;
            const float* ap = S + (s2 * 48 + hh * 24 + t);
            const float* vp = U + 3456 + o * Rn + s2 * Tn;
            float acc = 0.0f;
            #pragma unroll
            for (int j = 0; j < Tn; j++) acc = fmaf(ap[j * 96], vp[j], acc);
            U[idx] = acc;
        }
        __syncthreads();

        mmT<HIDn, HIDn, false>(U, Wo_l, bo_l, U + 5184, tid);
        __syncthreads();

        // LN1: h = LN(h + o)
        if (tid < Rn) {
            int r = tid;
            float m = 0.0f, q2 = 0.0f;
            #pragma unroll
            for (int k = 0; k < HIDn; k++) {
                float v = h[k * Rn + r] + U[5184 + k * Rn + r];
                h[k * Rn + r] = v;
                m += v; q2 += v * v;
            }
            m *= (1.0f / HIDn);
            float var = q2 * (1.0f / HIDn) - m * m;
            float rs = rsqrtf(var + 1e-5f);
            #pragma unroll
            for (int k = 0; k < HIDn; k++)
                h[k * Rn + r] = (h[k * Rn + r] - m) * rs * __ldg(g1_l + k) + __ldg(b1_l + k);
        }
        __syncthreads();

        // FFN
        mmT<HIDn, FFNn, true >(h, fW1_l, fb1_l, U, tid);
        __syncthreads();
        mmT<FFNn, HIDn, false>(U, fW2_l, fb2_l, S, tid);
        __syncthreads();

        // LN2: h = LN(h + f2)
        if (tid < Rn) {
            int r = tid;
            float m = 0.0f, q2 = 0.0f;
            #pragma unroll
            for (int k = 0; k < HIDn; k++) {
                float v = h[k * Rn + r] + S[k * Rn + r];
                h[k * Rn + r] = v;
                m += v; q2 += v * v;
            }
            m *= (1.0f / HIDn);
            float var = q2 * (1.0f / HIDn) - m * m;
            float rs = rsqrtf(var + 1e-5f);
            #pragma unroll
            for (int k = 0; k < HIDn; k++)
                h[k * Rn + r] = (h[k * Rn + r] - m) * rs * __ldg(g2_l + k) + __ldg(b2_l + k);
        }
        __syncthreads();
    }

    // ---- final fc + store ----
    if (tid < Rn) {
        int r = tid;
        int s2 = r / Tn, t = r % Tn;
        int n2 = nbase + s2;
        int b = n2 >> 9, c = n2 & (Cn - 1);
        float acc = __ldg(fcb);
        #pragma unroll
        for (int k = 0; k < HIDn; k++) acc = fmaf(h[k * Rn + r], __ldg(fcW + k), acc);
        out[(b * Tn + t) * Cn + c] = acc;
    }
}

// ---------------- launch ------------------------------------------------------
extern "C" void kernel_launch(void* const* d_in, const int* in_sizes, int n_in,
                              void* d_out, int out_size) {
    const float *pm, *ft, *W0, *W1, *cb, *tinW, *tinb, *Wq, *bq, *Wk, *bk,
                *Wv, *bv, *Wo, *bo, *g1, *b1, *fW1, *fb1, *fW2, *fb2,
                *g2, *b2, *fcW, *fcb;
    const int* ei;

    if (in_sizes[2] == 2 * EG) {
        pm  = (const float*)d_in[0];  ft  = (const float*)d_in[1];
        ei  = (const int*)  d_in[2];
        W0  = (const float*)d_in[3];  W1  = (const float*)d_in[4];
        cb  = (const float*)d_in[5];
        tinW= (const float*)d_in[6];  tinb= (const float*)d_in[7];
        Wq  = (const float*)d_in[8];  bq  = (const float*)d_in[9];
        Wk  = (const float*)d_in[10]; bk  = (const float*)d_in[11];
        Wv  = (const float*)d_in[12]; bv  = (const float*)d_in[13];
        Wo  = (const float*)d_in[14]; bo  = (const float*)d_in[15];
        g1  = (const float*)d_in[16]; b1  = (const float*)d_in[17];
        fW1 = (const float*)d_in[18]; fb1 = (const float*)d_in[19];
        fW2 = (const float*)d_in[20]; fb2 = (const float*)d_in[21];
        g2  = (const float*)d_in[22]; b2  = (const float*)d_in[23];
        fcW = (const float*)d_in[24]; fcb = (const float*)d_in[25];
    } else {
        pm  = (const float*)d_in[0];  ft  = (const float*)d_in[1];
        W0  = (const float*)d_in[2];  W1  = (const float*)d_in[3];
        cb  = (const float*)d_in[4];
        tinW= (const float*)d_in[5];  tinb= (const float*)d_in[6];
        Wq  = (const float*)d_in[7];  bq  = (const float*)d_in[8];
        Wk  = (const float*)d_in[9];  bk  = (const float*)d_in[10];
        Wv  = (const float*)d_in[11]; bv  = (const float*)d_in[12];
        Wo  = (const float*)d_in[13]; bo  = (const float*)d_in[14];
        g1  = (const float*)d_in[15]; b1  = (const float*)d_in[16];
        fW1 = (const float*)d_in[17]; fb1 = (const float*)d_in[18];
        fW2 = (const float*)d_in[19]; fb2 = (const float*)d_in[20];
        g2  = (const float*)d_in[21]; b2  = (const float*)d_in[22];
        fcW = (const float*)d_in[23]; fcb = (const float*)d_in[24];
        ei  = (const int*)  d_in[25];
    }

    k_count<<<Cn, 32>>>(ei);
    k_scan <<<1, Cn>>>();
    k_fill <<<Cn, 32>>>(ei);
    {
        int total = Nn * Tn * INF;
        k_pack<<<(total + 255) / 256, 256>>>(pm, ft);
    }
    k_mega<<<Nn / SEQ, NT>>>(W0, W1, cb, tinW, tinb,
                             Wq, bq, Wk, bk, Wv, bv, Wo, bo,
                             g1, b1, fW1, fb1, fW2, fb2, g2, b2,
                             fcW, fcb, (float*)d_out);
}

// round 7
// speedup vs baseline: 2.4063x; 1.3194x over previous
#include <cuda_runtime.h>
#include <math.h>
#include <stdint.h>

#define Bn   32
#define Tn   24
#define Cn   512
#define Nn   (Bn*Cn)          // 16384
#define INF  14
#define HIDn 36
#define FFNn 144
#define HDn  18
#define EG   8192
#define SEQ  2
#define Rn   (SEQ*Tn)         // 48 rows per CTA
#define NT   128

// ---------------- scratch (device globals) -----------------------------------
__device__ float d_xn [Nn*Tn*INF];   // first-half features, [N][T][14] (t*14+f)
__device__ float d_xn2[Nn*Tn*INF];   // second-half features
__device__ int   d_deg[Cn];
__device__ int   d_colcnt[Cn];
__device__ int   d_off[Cn+1];
__device__ float d_dinv[Cn];
__device__ int   d_brow[EG];
__device__ float d_bw[EG];

// ---------------- K1: per-node degree (rows) and col counts ------------------
__global__ void k_count(const int* __restrict__ ei) {
    int c = blockIdx.x, lane = threadIdx.x;
    int cr = 0, cc = 0;
    for (int e = lane; e < EG; e += 32) {
        cr += (ei[e]      == c);
        cc += (ei[EG + e] == c);
    }
    #pragma unroll
    for (int o = 16; o; o >>= 1) {
        cr += __shfl_down_sync(0xffffffffu, cr, o);
        cc += __shfl_down_sync(0xffffffffu, cc, o);
    }
    if (lane == 0) { d_deg[c] = cr; d_colcnt[c] = cc; }
}

// ---------------- K2: scan col counts -> CSR offsets; dinv --------------------
__global__ void k_scan() {
    __shared__ int s[Cn];
    int t = threadIdx.x;
    s[t] = d_colcnt[t];
    __syncthreads();
    for (int o = 1; o < Cn; o <<= 1) {
        int v = (t >= o) ? s[t - o] : 0;
        __syncthreads();
        s[t] += v;
        __syncthreads();
    }
    d_off[t + 1] = s[t];
    if (t == 0) d_off[0] = 0;
    int dg = d_deg[t];
    d_dinv[t] = (dg > 0) ? (1.0f / sqrtf((float)dg)) : 0.0f;
}

// ---------------- K3: fill CSR buckets, stable in edge order ------------------
__global__ void k_fill(const int* __restrict__ ei) {
    int c = blockIdx.x, lane = threadIdx.x;
    int base = d_off[c];
    float dc = d_dinv[c];
    for (int e0 = 0; e0 < EG; e0 += 32) {
        int e = e0 + lane;
        int col = ei[EG + e];
        bool m = (col == c);
        unsigned mask = __ballot_sync(0xffffffffu, m);
        if (m) {
            int pos = base + __popc(mask & ((1u << lane) - 1u));
            int r = ei[e];
            d_brow[pos] = r;
            d_bw[pos]   = -(d_dinv[r] * dc);
        }
        base += __popc(mask);
    }
}

// ---------------- K4: pack xn / xn2 into [N][T][14] ---------------------------
__global__ void k_pack(const float* __restrict__ pm, const float* __restrict__ ft) {
    int idx = blockIdx.x * blockDim.x + threadIdx.x;
    if (idx >= Nn * Tn * INF) return;
    int f  = idx % INF;
    int rt = idx / INF;
    int t  = rt % Tn;
    int n  = rt / Tn;
    int b  = n >> 9, c = n & (Cn - 1);
    float v1, v2;
    if (f == 0) {
        v1 = pm[(b * Tn + t) * Cn + c];
        v2 = v1;
    } else {
        v1 = ft[((b * 2 * Tn + t)       * Cn + c) * 13 + (f - 1)];
        v2 = ft[((b * 2 * Tn + Tn + t)  * Cn + c) * 13 + (f - 1)];
    }
    d_xn [idx] = v1;
    d_xn2[idx] = v2;
}

// ---------------- packed f32x2 helpers ----------------------------------------
__device__ __forceinline__ uint64_t pack2(float v) {
    uint64_t r;
    asm("mov.b64 %0, {%1, %1};" : "=l"(r) : "f"(v));
    return r;
}
__device__ __forceinline__ void fma2(uint64_t& acc, uint64_t a, uint64_t b) {
    asm("fma.rn.f32x2 %0, %1, %2, %0;" : "+l"(acc) : "l"(a), "l"(b));
}
__device__ __forceinline__ float2 unpack2(uint64_t v) {
    float lo, hi;
    asm("mov.b64 {%0, %1}, %2;" : "=f"(lo), "=f"(hi) : "l"(v));
    return make_float2(lo, hi);
}

// ---------------- register-tiled matmul --------------------------------------
// sOUT[NOUT][48] = W^T @ sIN (+bias).  sIN col-major [KD][48]; W row-major
// [KD][NOUT].  4x4 tiles; rows as f32x2 pairs via 128-bit LDS.
template<int KD, int NOUT, bool RELU>
__device__ __forceinline__ void mmT(const float* __restrict__ sIN,
                                    const float* __restrict__ W,
                                    const float* __restrict__ bias,
                                    float* __restrict__ sOUT, int tid) {
    constexpr int RG = Rn / 4;                    // 12 row groups
    constexpr int TILES = RG * (NOUT / 4);
    for (int tile = tid; tile < TILES; tile += NT) {
        int rg = tile % RG, cg = tile / RG;
        const float* aP = sIN + rg * 4;
        const float* wP = W + cg * 4;
        uint64_t acc[8];
        #pragma unroll
        for (int j = 0; j < 4; j++) {
            uint64_t bp = pack2(__ldg(bias + cg * 4 + j));
            acc[2 * j]     = bp;
            acc[2 * j + 1] = bp;
        }
        #pragma unroll 4
        for (int k = 0; k < KD; k++) {
            ulonglong2 av = *(const ulonglong2*)(aP + k * Rn);
            float4 w = __ldg((const float4*)(wP + k * NOUT));
            uint64_t w0 = pack2(w.x), w1 = pack2(w.y), w2 = pack2(w.z), w3 = pack2(w.w);
            fma2(acc[0], av.x, w0); fma2(acc[1], av.y, w0);
            fma2(acc[2], av.x, w1); fma2(acc[3], av.y, w1);
            fma2(acc[4], av.x, w2); fma2(acc[5], av.y, w2);
            fma2(acc[6], av.x, w3); fma2(acc[7], av.y, w3);
        }
        #pragma unroll
        for (int j = 0; j < 4; j++) {
            float2 lo = unpack2(acc[2 * j]);
            float2 hi = unpack2(acc[2 * j + 1]);
            float4 c;
            c.x = lo.x; c.y = lo.y; c.z = hi.x; c.w = hi.y;
            if (RELU) {
                c.x = fmaxf(c.x, 0.f); c.y = fmaxf(c.y, 0.f);
                c.z = fmaxf(c.z, 0.f); c.w = fmaxf(c.w, 0.f);
            }
            *(float4*)(sOUT + (cg * 4 + j) * Rn + rg * 4) = c;
        }
    }
}

// ---------------- LN helper: 96 threads, 2 per row, shfl combine --------------
__device__ __forceinline__ void layernorm2(float* __restrict__ h,
                                           const float* __restrict__ res,
                                           const float* __restrict__ g,
                                           const float* __restrict__ bb,
                                           int tid) {
    if (tid < 96) {
        int r = tid >> 1, half = tid & 1;
        float vloc[18];
        float m = 0.0f, q2 = 0.0f;
        #pragma unroll
        for (int kk = 0; kk < 18; kk++) {
            int k = half * 18 + kk;
            float v = h[k * Rn + r] + res[k * Rn + r];
            vloc[kk] = v;
            m += v; q2 += v * v;
        }
        m  += __shfl_xor_sync(0xffffffffu, m, 1);
        q2 += __shfl_xor_sync(0xffffffffu, q2, 1);
        m *= (1.0f / HIDn);
        float var = q2 * (1.0f / HIDn) - m * m;
        float rs = rsqrtf(var + 1e-5f);
        #pragma unroll
        for (int kk = 0; kk < 18; kk++) {
            int k = half * 18 + kk;
            h[k * Rn + r] = (vloc[kk] - m) * rs * __ldg(g + k) + __ldg(bb + k);
        }
    }
}

// ---------------- K5: mega-kernel — 2 sequences per CTA, static smem ----------
__global__ __launch_bounds__(NT, 5)
void k_mega(const float* __restrict__ W0,  const float* __restrict__ W1,
            const float* __restrict__ cb,
            const float* __restrict__ tinW, const float* __restrict__ tinb,
            const float* __restrict__ Wq, const float* __restrict__ bq,
            const float* __restrict__ Wk, const float* __restrict__ bk,
            const float* __restrict__ Wv, const float* __restrict__ bv,
            const float* __restrict__ Wo, const float* __restrict__ bo,
            const float* __restrict__ g1, const float* __restrict__ b1,
            const float* __restrict__ fW1, const float* __restrict__ fb1,
            const float* __restrict__ fW2, const float* __restrict__ fb2,
            const float* __restrict__ g2, const float* __restrict__ b2,
            const float* __restrict__ fcW, const float* __restrict__ fcb,
            float* __restrict__ out) {
    __shared__ __align__(16) float sh_h[HIDn * Rn];     // 1728
    __shared__ __align__(16) float sh_U[FFNn * Rn];     // 6912
    __shared__ __align__(16) float sh_S[2304];

    float* h = sh_h;
    float* U = sh_U;
    float* S = sh_S;
    float* x   = U;            //  672
    float* tx  = U + 672;      //  672
    float* cat = U + 1344;     // 1344

    const int tid = threadIdx.x;
    const int nbase = blockIdx.x * SEQ;

    // ---- stage self tiles (col-major [14][48]) ----
    for (int idx = tid; idx < SEQ * Tn * INF; idx += NT) {
        int s2 = idx / 336, u = idx % 336;
        int t = u / INF, f = u % INF;
        int n2 = nbase + s2;
        x  [f * Rn + s2 * Tn + t] = d_xn [n2 * 336 + u];
        cat[f * Rn + s2 * Tn + t] = d_xn2[n2 * 336 + u];
    }

    // ---- ChebConv gather: 64 threads per sequence ----
    {
        int s2 = tid >> 6, l = tid & 63;
        int n2 = nbase + s2;
        int b = n2 >> 9, c = n2 & (Cn - 1);
        float acc[6];
        #pragma unroll
        for (int i = 0; i < 6; i++) acc[i] = 0.0f;
        int start = d_off[c], end = d_off[c + 1];
        for (int e = start; e < end; e++) {
            int   rr = __ldg(d_brow + e);
            float w  = __ldg(d_bw + e);
            const float* nb = d_xn + (b * Cn + rr) * 336;
            #pragma unroll
            for (int i = 0; i < 6; i++) {
                int u = l + i * 64;
                if (u < 336) acc[i] = fmaf(w, nb[u], acc[i]);
            }
        }
        #pragma unroll
        for (int i = 0; i < 6; i++) {
            int u = l + i * 64;
            if (u < 336) {
                int t = u / INF, f = u % INF;
                tx[f * Rn + s2 * Tn + t] = acc[i];
            }
        }
    }
    __syncthreads();

    // ---- gate: cat[:,14:] = sigmoid(x @ W0 + tx @ W1 + cb) ----
    for (int idx = tid; idx < Rn * INF; idx += NT) {
        int r = idx % Rn, j = idx / Rn;
        float sacc = __ldg(cb + j);
        #pragma unroll
        for (int f = 0; f < INF; f++) {
            sacc = fmaf(x [f * Rn + r], __ldg(W0 + f * INF + j), sacc);
            sacc = fmaf(tx[f * Rn + r], __ldg(W1 + f * INF + j), sacc);
        }
        cat[(INF + j) * Rn + r] = 1.0f / (1.0f + expf(-sacc));
    }
    __syncthreads();

    // ---- h = cat @ tinW + tinb ----
    mmT<28, HIDn, false>(cat, tinW, tinb, h, tid);
    __syncthreads();

    // ---- sinusoidal PE ----
    for (int idx = tid; idx < HIDn * Rn; idx += NT) {
        int r = idx % Rn, o = idx / Rn;
        int t = r % Tn;
        float div = expf(-9.210340371976184f * (float)(o & ~1) / (float)HIDn);
        float ang = (float)t * div;
        h[idx] += (o & 1) ? cosf(ang) : sinf(ang);
    }
    __syncthreads();

    // ---- 2 encoder layers ----
    const float scale = 0.23570226039551584f;  // 1/sqrt(18)
    #pragma unroll 1
    for (int l = 0; l < 2; l++) {
        const float* Wq_l = Wq + l * HIDn * HIDn;  const float* bq_l = bq + l * HIDn;
        const float* Wk_l = Wk + l * HIDn * HIDn;  const float* bk_l = bk + l * HIDn;
        const float* Wv_l = Wv + l * HIDn * HIDn;  const float* bv_l = bv + l * HIDn;
        const float* Wo_l = Wo + l * HIDn * HIDn;  const float* bo_l = bo + l * HIDn;
        const float* g1_l = g1 + l * HIDn;         const float* b1_l = b1 + l * HIDn;
        const float* g2_l = g2 + l * HIDn;         const float* b2_l = b2 + l * HIDn;
        const float* fW1_l = fW1 + l * HIDn * FFNn; const float* fb1_l = fb1 + l * FFNn;
        const float* fW2_l = fW2 + l * FFNn * HIDn; const float* fb2_l = fb2 + l * HIDn;

        mmT<HIDn, HIDn, false>(h, Wq_l, bq_l, U,        tid);
        mmT<HIDn, HIDn, false>(h, Wk_l, bk_l, U + 1728, tid);
        mmT<HIDn, HIDn, false>(h, Wv_l, bv_l, U + 3456, tid);
        __syncthreads();

        // ---- scores: register-tiled 24x24x18 GEMMs per (s2,hh) block ----
        // S[j*96 + row], row = s2*48 + hh*24 + i.  144 tiles of 4i x 4j.
        for (int tile = tid; tile < 144; tile += NT) {
            int bs = tile / 36, rem = tile % 36;
            int ig = rem % 6, jg = rem / 6;
            int s2 = bs >> 1, hh = bs & 1;
            const float* qb = U        + hh * HDn * Rn + s2 * Tn + ig * 4;
            const float* kb = U + 1728 + hh * HDn * Rn + s2 * Tn + jg * 4;
            uint64_t acc[8];
            #pragma unroll
            for (int i = 0; i < 8; i++) acc[i] = 0ull;
            #pragma unroll 2
            for (int d = 0; d < HDn; d++) {
                ulonglong2 qv = *(const ulonglong2*)(qb + d * Rn);
                float4 kv = *(const float4*)(kb + d * Rn);
                uint64_t k0 = pack2(kv.x), k1 = pack2(kv.y), k2 = pack2(kv.z), k3 = pack2(kv.w);
                fma2(acc[0], qv.x, k0); fma2(acc[1], qv.y, k0);
                fma2(acc[2], qv.x, k1); fma2(acc[3], qv.y, k1);
                fma2(acc[4], qv.x, k2); fma2(acc[5], qv.y, k2);
                fma2(acc[6], qv.x, k3); fma2(acc[7], qv.y, k3);
            }
            int rowbase = s2 * 48 + hh * 24 + ig * 4;
            #pragma unroll
            for (int jj = 0; jj < 4; jj++) {
                float2 lo = unpack2(acc[2 * jj]);
                float2 hi = unpack2(acc[2 * jj + 1]);
                *(float4*)(S + (jg * 4 + jj) * 96 + rowbase) =
                    make_float4(lo.x * scale, lo.y * scale, hi.x * scale, hi.y * scale);
            }
        }
        __syncthreads();

        // softmax over j (row per thread; stride-96)
        if (tid < 96) {
            float m = S[tid];
            #pragma unroll
            for (int j = 1; j < Tn; j++) m = fmaxf(m, S[j * 96 + tid]);
            float sum = 0.0f;
            #pragma unroll
            for (int j = 0; j < Tn; j++) {
                float e = expf(S[j * 96 + tid] - m);
                S[j * 96 + tid] = e;
                sum += e;
            }
            float inv = 1.0f / sum;
            #pragma unroll
            for (int j = 0; j < Tn; j++) S[j * 96 + tid] *= inv;
        }
        __syncthreads();

        // ---- attn out: register-tiled A@V -> q region (U[0..1728)) ----
        // 144 tiles: s2(2) x og(12, 3 o's each, head-pure) x tg(6, 4 t's each)
        for (int tile = tid; tile < 144; tile += NT) {
            int s2 = tile / 72, rem = tile % 72;
            int tg = rem % 6, og = rem / 6;     // og 0..11
            int hh = og / 6;
            const float* ab = S + s2 * 48 + hh * 24 + tg * 4;       // + j*96
            const float* vb = U + 3456 + (og * 3) * Rn + s2 * Tn;   // + oo*Rn + j
            uint64_t acc[6];
            #pragma unroll
            for (int i = 0; i < 6; i++) acc[i] = 0ull;
            #pragma unroll 4
            for (int j = 0; j < Tn; j++) {
                ulonglong2 avv = *(const ulonglong2*)(ab + j * 96);
                uint64_t p0 = pack2(vb[j]);
                uint64_t p1 = pack2(vb[Rn + j]);
                uint64_t p2 = pack2(vb[2 * Rn + j]);
                fma2(acc[0], avv.x, p0); fma2(acc[1], avv.y, p0);
                fma2(acc[2], avv.x, p1); fma2(acc[3], avv.y, p1);
                fma2(acc[4], avv.x, p2); fma2(acc[5], avv.y, p2);
            }
            #pragma unroll
            for (int oo = 0; oo < 3; oo++) {
                float2 lo = unpack2(acc[2 * oo]);
                float2 hi = unpack2(acc[2 * oo + 1]);
                *(float4*)(U + (og * 3 + oo) * Rn + s2 * Tn + tg * 4) =
                    make_float4(lo.x, lo.y, hi.x, hi.y);
            }
        }
        __syncthreads();

        mmT<HIDn, HIDn, false>(U, Wo_l, bo_l, U + 5184, tid);
        __syncthreads();

        // LN1: h = LN(h + o)
        layernorm2(h, U + 5184, g1_l, b1_l, tid);
        __syncthreads();

        // FFN
        mmT<HIDn, FFNn, true >(h, fW1_l, fb1_l, U, tid);
        __syncthreads();
        mmT<FFNn, HIDn, false>(U, fW2_l, fb2_l, S, tid);
        __syncthreads();

        // LN2: h = LN(h + f2)
        layernorm2(h, S, g2_l, b2_l, tid);
        __syncthreads();
    }

    // ---- final fc + store ----
    if (tid < Rn) {
        int r = tid;
        int s2 = r / Tn, t = r % Tn;
        int n2 = nbase + s2;
        int b = n2 >> 9, c = n2 & (Cn - 1);
        float acc = __ldg(fcb);
        #pragma unroll
        for (int k = 0; k < HIDn; k++) acc = fmaf(h[k * Rn + r], __ldg(fcW + k), acc);
        out[(b * Tn + t) * Cn + c] = acc;
    }
}

// ---------------- launch ------------------------------------------------------
extern "C" void kernel_launch(void* const* d_in, const int* in_sizes, int n_in,
                              void* d_out, int out_size) {
    const float *pm, *ft, *W0, *W1, *cb, *tinW, *tinb, *Wq, *bq, *Wk, *bk,
                *Wv, *bv, *Wo, *bo, *g1, *b1, *fW1, *fb1, *fW2, *fb2,
                *g2, *b2, *fcW, *fcb;
    const int* ei;

    if (in_sizes[2] == 2 * EG) {
        pm  = (const float*)d_in[0];  ft  = (const float*)d_in[1];
        ei  = (const int*)  d_in[2];
        W0  = (const float*)d_in[3];  W1  = (const float*)d_in[4];
        cb  = (const float*)d_in[5];
        tinW= (const float*)d_in[6];  tinb= (const float*)d_in[7];
        Wq  = (const float*)d_in[8];  bq  = (const float*)d_in[9];
        Wk  = (const float*)d_in[10]; bk  = (const float*)d_in[11];
        Wv  = (const float*)d_in[12]; bv  = (const float*)d_in[13];
        Wo  = (const float*)d_in[14]; bo  = (const float*)d_in[15];
        g1  = (const float*)d_in[16]; b1  = (const float*)d_in[17];
        fW1 = (const float*)d_in[18]; fb1 = (const float*)d_in[19];
        fW2 = (const float*)d_in[20]; fb2 = (const float*)d_in[21];
        g2  = (const float*)d_in[22]; b2  = (const float*)d_in[23];
        fcW = (const float*)d_in[24]; fcb = (const float*)d_in[25];
    } else {
        pm  = (const float*)d_in[0];  ft  = (const float*)d_in[1];
        W0  = (const float*)d_in[2];  W1  = (const float*)d_in[3];
        cb  = (const float*)d_in[4];
        tinW= (const float*)d_in[5];  tinb= (const float*)d_in[6];
        Wq  = (const float*)d_in[7];  bq  = (const float*)d_in[8];
        Wk  = (const float*)d_in[9];  bk  = (const float*)d_in[10];
        Wv  = (const float*)d_in[11]; bv  = (const float*)d_in[12];
        Wo  = (const float*)d_in[13]; bo  = (const float*)d_in[14];
        g1  = (const float*)d_in[15]; b1  = (const float*)d_in[16];
        fW1 = (const float*)d_in[17]; fb1 = (const float*)d_in[18];
        fW2 = (const float*)d_in[19]; fb2 = (const float*)d_in[20];
        g2  = (const float*)d_in[21]; b2  = (const float*)d_in[22];
        fcW = (const float*)d_in[23]; fcb = (const float*)d_in[24];
        ei  = (const int*)  d_in[25];
    }

    k_count<<<Cn, 32>>>(ei);
    k_scan <<<1, Cn>>>();
    k_fill <<<Cn, 32>>>(ei);
    {
        int total = Nn * Tn * INF;
        k_pack<<<(total + 255) / 256, 256>>>(pm, ft);
    }
    k_mega<<<Nn / SEQ, NT>>>(W0, W1, cb, tinW, tinb,
                             Wq, bq, Wk, bk, Wv, bv, Wo, bo,
                             g1, b1, fW1, fb1, fW2, fb2, g2, b2,
                             fcW, fcb, (float*)d_out);
}